// round 10
// baseline (speedup 1.0000x reference)
#include <cuda_runtime.h>
#include <cuda_fp16.h>
#include <math.h>

#define NN 100000
#define EE 1600000

// ---- scratch (__device__ globals; no allocations allowed) ----
__device__ __align__(16) __half g_Yh[NN * 32];    // [Y0(16h)|Y1(16h)] per node, 64B row
__device__ __align__(16) float  g_R1[NN * 16];    // x@root1 + b1
__device__ __align__(16) __half g_acc1h[NN * 16]; // layer-1 fp16 accumulator, 32B row
__device__ float g_deg[NN];                       // in-degree; ZERO invariant between launches
__device__ __align__(16) __half g_Zh[NN * 32];    // [Z0(10h)+pad6 | Z1(10h)+pad6], 64B row
__device__ __align__(16) float  g_R2[NN * 10];    // h@root2 + b2
__device__ __align__(16) __half g_acc2h[NN * 16]; // layer-2 fp16 accumulator, 32B row

__device__ __forceinline__ void red_add_v4h2(__half* a, unsigned p0, unsigned p1,
                                             unsigned p2, unsigned p3) {
    asm volatile("red.global.add.noftz.v4.f16x2 [%0], {%1, %2, %3, %4};"
                 :: "l"(a), "r"(p0), "r"(p1), "r"(p2), "r"(p3) : "memory");
}
__device__ __forceinline__ unsigned packh2(float a, float b) {
    __half2 h = __floats2half2_rn(a, b);
    return *reinterpret_cast<unsigned*>(&h);
}
__device__ __forceinline__ float2 unph2(unsigned u) {
    __half2 h = *reinterpret_cast<__half2*>(&u);
    return __half22float2(h);
}

// ---------------------------------------------------------------------------
// Node kernel 1: Yh = fp16{x@W1[0], x@W1[1]}, R1 = x@root1 + b1; zero acc1h;
// then grid-stride deg histogram (deg was zeroed by previous out_kernel /
// module-load zero-init).
// ---------------------------------------------------------------------------
__global__ void node1_kernel(const float* __restrict__ x,
                             const float* __restrict__ W1,
                             const float* __restrict__ root1,
                             const float* __restrict__ b1,
                             const int* __restrict__ ei)
{
    __shared__ float sW[1024];   // W1[k][i][o]
    __shared__ float sR[512];    // root1[i][o]
    __shared__ float sB[16];
    for (int t = threadIdx.x; t < 1024; t += blockDim.x) sW[t] = W1[t];
    for (int t = threadIdx.x; t < 512;  t += blockDim.x) sR[t] = root1[t];
    if (threadIdx.x < 16) sB[threadIdx.x] = b1[threadIdx.x];
    __syncthreads();

    int n = blockIdx.x * blockDim.x + threadIdx.x;
    if (n < NN) {
        float xv[32];
        const float4* xp = (const float4*)(x + (size_t)n * 32);
        #pragma unroll
        for (int i = 0; i < 8; i++) {
            float4 t = xp[i];
            xv[4*i+0] = t.x; xv[4*i+1] = t.y; xv[4*i+2] = t.z; xv[4*i+3] = t.w;
        }

        float y0v[16], y1v[16];
        float* Rp = g_R1 + (size_t)n * 16;
        for (int o = 0; o < 16; o++) {
            float y0 = 0.f, y1 = 0.f, r = sB[o];
            #pragma unroll
            for (int i = 0; i < 32; i++) {
                y0 = fmaf(xv[i], sW[i * 16 + o], y0);
                y1 = fmaf(xv[i], sW[512 + i * 16 + o], y1);
                r  = fmaf(xv[i], sR[i * 16 + o], r);
            }
            y0v[o] = y0; y1v[o] = y1; Rp[o] = r;
        }

        uint4* yo = (uint4*)(g_Yh + (size_t)n * 32);
        #pragma unroll
        for (int c = 0; c < 2; c++)
            yo[c] = make_uint4(packh2(y0v[8*c+0], y0v[8*c+1]), packh2(y0v[8*c+2], y0v[8*c+3]),
                               packh2(y0v[8*c+4], y0v[8*c+5]), packh2(y0v[8*c+6], y0v[8*c+7]));
        #pragma unroll
        for (int c = 0; c < 2; c++)
            yo[2+c] = make_uint4(packh2(y1v[8*c+0], y1v[8*c+1]), packh2(y1v[8*c+2], y1v[8*c+3]),
                                 packh2(y1v[8*c+4], y1v[8*c+5]), packh2(y1v[8*c+6], y1v[8*c+7]));

        uint4 z4 = make_uint4(0u, 0u, 0u, 0u);
        uint4* ap = (uint4*)(g_acc1h + (size_t)n * 16);
        ap[0] = z4; ap[1] = z4;
    }

    // deg histogram (fire-and-forget REDs, overlapped with other blocks' math)
    int stride = gridDim.x * blockDim.x;
    for (int e = blockIdx.x * blockDim.x + threadIdx.x; e < EE; e += stride) {
        int d = ei[EE + e];
        if ((unsigned)d < NN) atomicAdd(&g_deg[d], 1.0f);
    }
}

// ---------------------------------------------------------------------------
// Edge kernel 1 (quad): 4 lanes/edge, lane j loads row chunk j (16B) -> the
// whole 64B row in ONE LDG instruction per warp (1 line-touch/edge). shfl_xor
// lane j^2 exchanges Y1 chunks to Y0 lanes; lanes 0,1 lerp + red 16B each.
// ---------------------------------------------------------------------------
__global__ void edge1_kernel(const int* __restrict__ ei,
                             const float* __restrict__ attr)
{
    int gid = blockIdx.x * blockDim.x + threadIdx.x;
    int e = gid >> 2;          // grid sized exactly: EE*4 threads
    int j = gid & 3;

    int s = ei[e];
    int d = ei[EE + e];
    bool ok = ((unsigned)s < NN) && ((unsigned)d < NN);
    if (!ok) s = 0;            // keep shuffle participation; suppress red below
    float v  = attr[e];
    float c0 = fmaxf(0.f, 1.f - fabsf(v));
    float c1 = fmaxf(0.f, 1.f - fabsf(v - 1.f));

    uint4 Q = ((const uint4*)(g_Yh + (size_t)s * 32))[j];
    uint4 P;
    P.x = __shfl_xor_sync(0xffffffffu, Q.x, 2);
    P.y = __shfl_xor_sync(0xffffffffu, Q.y, 2);
    P.z = __shfl_xor_sync(0xffffffffu, Q.z, 2);
    P.w = __shfl_xor_sync(0xffffffffu, Q.w, 2);

    if (j < 2 && ok) {
        // Q = Y0 halves [8j..8j+8), P = Y1 halves [8j..8j+8)
        float2 a0 = unph2(Q.x), a1 = unph2(Q.y), a2 = unph2(Q.z), a3 = unph2(Q.w);
        float2 b0 = unph2(P.x), b1 = unph2(P.y), b2 = unph2(P.z), b3 = unph2(P.w);
        unsigned p0 = packh2(c0*a0.x + c1*b0.x, c0*a0.y + c1*b0.y);
        unsigned p1 = packh2(c0*a1.x + c1*b1.x, c0*a1.y + c1*b1.y);
        unsigned p2 = packh2(c0*a2.x + c1*b2.x, c0*a2.y + c1*b2.y);
        unsigned p3 = packh2(c0*a3.x + c1*b3.x, c0*a3.y + c1*b3.y);
        red_add_v4h2(g_acc1h + (size_t)d * 16 + 8 * j, p0, p1, p2, p3);
    }
}

// ---------------------------------------------------------------------------
// Node kernel 2: h = elu(acc1h/deg + R1); Zh fp16 padded rows; zero acc2h
// ---------------------------------------------------------------------------
__global__ void node2_kernel(const float* __restrict__ W2,
                             const float* __restrict__ root2,
                             const float* __restrict__ b2)
{
    __shared__ float sW[320];
    __shared__ float sR[160];
    __shared__ float sB[10];
    for (int t = threadIdx.x; t < 320; t += blockDim.x) sW[t] = W2[t];
    for (int t = threadIdx.x; t < 160; t += blockDim.x) sR[t] = root2[t];
    if (threadIdx.x < 10) sB[threadIdx.x] = b2[threadIdx.x];
    __syncthreads();

    int n = blockIdx.x * blockDim.x + threadIdx.x;
    if (n >= NN) return;

    float inv = 1.f / fmaxf(g_deg[n], 1.f);
    const uint4* ah = (const uint4*)(g_acc1h + (size_t)n * 16);
    uint4 u0 = ah[0], u1 = ah[1];
    float ac[16];
    {
        float2 t;
        t = unph2(u0.x); ac[0]=t.x; ac[1]=t.y;
        t = unph2(u0.y); ac[2]=t.x; ac[3]=t.y;
        t = unph2(u0.z); ac[4]=t.x; ac[5]=t.y;
        t = unph2(u0.w); ac[6]=t.x; ac[7]=t.y;
        t = unph2(u1.x); ac[8]=t.x; ac[9]=t.y;
        t = unph2(u1.y); ac[10]=t.x; ac[11]=t.y;
        t = unph2(u1.z); ac[12]=t.x; ac[13]=t.y;
        t = unph2(u1.w); ac[14]=t.x; ac[15]=t.y;
    }
    const float* r1 = g_R1 + (size_t)n * 16;
    float h[16];
    #pragma unroll
    for (int o = 0; o < 16; o++) {
        float t = ac[o] * inv + r1[o];
        h[o] = (t > 0.f) ? t : expm1f(t);       // ELU alpha=1
    }

    float z0v[16], z1v[16];
    #pragma unroll
    for (int i = 0; i < 16; i++) { z0v[i] = 0.f; z1v[i] = 0.f; }
    float* r2 = g_R2 + (size_t)n * 10;
    for (int o = 0; o < 10; o++) {
        float z0 = 0.f, z1 = 0.f, r = sB[o];
        #pragma unroll
        for (int i = 0; i < 16; i++) {
            z0 = fmaf(h[i], sW[i * 10 + o], z0);
            z1 = fmaf(h[i], sW[160 + i * 10 + o], z1);
            r  = fmaf(h[i], sR[i * 10 + o], r);
        }
        z0v[o] = z0; z1v[o] = z1; r2[o] = r;
    }

    uint4* zo = (uint4*)(g_Zh + (size_t)n * 32);
    #pragma unroll
    for (int c = 0; c < 2; c++)
        zo[c] = make_uint4(packh2(z0v[8*c+0], z0v[8*c+1]), packh2(z0v[8*c+2], z0v[8*c+3]),
                           packh2(z0v[8*c+4], z0v[8*c+5]), packh2(z0v[8*c+6], z0v[8*c+7]));
    #pragma unroll
    for (int c = 0; c < 2; c++)
        zo[2+c] = make_uint4(packh2(z1v[8*c+0], z1v[8*c+1]), packh2(z1v[8*c+2], z1v[8*c+3]),
                             packh2(z1v[8*c+4], z1v[8*c+5]), packh2(z1v[8*c+6], z1v[8*c+7]));

    uint4 z4 = make_uint4(0u, 0u, 0u, 0u);
    uint4* ap = (uint4*)(g_acc2h + (size_t)n * 16);
    ap[0] = z4; ap[1] = z4;
}

// ---------------------------------------------------------------------------
// Edge kernel 2 (quad): identical structure; Z row 64B (pads are zero).
// ---------------------------------------------------------------------------
__global__ void edge2_kernel(const int* __restrict__ ei,
                             const float* __restrict__ attr)
{
    int gid = blockIdx.x * blockDim.x + threadIdx.x;
    int e = gid >> 2;
    int j = gid & 3;

    int s = ei[e];
    int d = ei[EE + e];
    bool ok = ((unsigned)s < NN) && ((unsigned)d < NN);
    if (!ok) s = 0;
    float v  = attr[e];
    float c0 = fmaxf(0.f, 1.f - fabsf(v));
    float c1 = fmaxf(0.f, 1.f - fabsf(v - 1.f));

    uint4 Q = ((const uint4*)(g_Zh + (size_t)s * 32))[j];
    uint4 P;
    P.x = __shfl_xor_sync(0xffffffffu, Q.x, 2);
    P.y = __shfl_xor_sync(0xffffffffu, Q.y, 2);
    P.z = __shfl_xor_sync(0xffffffffu, Q.z, 2);
    P.w = __shfl_xor_sync(0xffffffffu, Q.w, 2);

    if (j < 2 && ok) {
        float2 a0 = unph2(Q.x), a1 = unph2(Q.y), a2 = unph2(Q.z), a3 = unph2(Q.w);
        float2 b0 = unph2(P.x), b1 = unph2(P.y), b2 = unph2(P.z), b3 = unph2(P.w);
        unsigned p0 = packh2(c0*a0.x + c1*b0.x, c0*a0.y + c1*b0.y);
        unsigned p1 = packh2(c0*a1.x + c1*b1.x, c0*a1.y + c1*b1.y);
        unsigned p2 = packh2(c0*a2.x + c1*b2.x, c0*a2.y + c1*b2.y);
        unsigned p3 = packh2(c0*a3.x + c1*b3.x, c0*a3.y + c1*b3.y);
        red_add_v4h2(g_acc2h + (size_t)d * 16 + 8 * j, p0, p1, p2, p3);
    }
}

// ---------------------------------------------------------------------------
// Output kernel: log_softmax(acc2h/deg + R2); re-zero deg for next launch
// ---------------------------------------------------------------------------
__global__ void out_kernel(float* __restrict__ out)
{
    int n = blockIdx.x * blockDim.x + threadIdx.x;
    if (n >= NN) return;

    float inv = 1.f / fmaxf(g_deg[n], 1.f);
    const uint4* ah = (const uint4*)(g_acc2h + (size_t)n * 16);
    uint4 u0 = ah[0], u1 = ah[1];
    float ac[10];
    {
        float2 t;
        t = unph2(u0.x); ac[0]=t.x; ac[1]=t.y;
        t = unph2(u0.y); ac[2]=t.x; ac[3]=t.y;
        t = unph2(u0.z); ac[4]=t.x; ac[5]=t.y;
        t = unph2(u0.w); ac[6]=t.x; ac[7]=t.y;
        t = unph2(u1.x); ac[8]=t.x; ac[9]=t.y;
    }
    const float* r2 = g_R2 + (size_t)n * 10;
    float o[10];
    #pragma unroll
    for (int j = 0; j < 10; j++) o[j] = ac[j] * inv + r2[j];

    float mx = o[0];
    #pragma unroll
    for (int j = 1; j < 10; j++) mx = fmaxf(mx, o[j]);
    float sum = 0.f;
    #pragma unroll
    for (int j = 0; j < 10; j++) sum += expf(o[j] - mx);
    float lse = mx + logf(sum);

    float* op = out + (size_t)n * 10;
    #pragma unroll
    for (int j = 0; j < 10; j++) op[j] = o[j] - lse;

    g_deg[n] = 0.f;   // restore zero invariant for next launch
}

// ---------------------------------------------------------------------------
extern "C" void kernel_launch(void* const* d_in, const int* in_sizes, int n_in,
                              void* d_out, int out_size)
{
    (void)out_size;
    int ix = -1, iei = -1, iattr = -1, iW1 = -1, ir1 = -1, ib1 = -1,
        iW2 = -1, ir2 = -1, ib2 = -1;
    int big[2]; int nbig = 0;
    for (int i = 0; i < n_in; i++) {
        switch (in_sizes[i]) {
            case 3200000: if (nbig < 2) big[nbig++] = i; break;
            case 1600000: iattr = i; break;
            case 1024:    iW1 = i; break;
            case 512:     ir1 = i; break;
            case 16:      ib1 = i; break;
            case 320:     iW2 = i; break;
            case 160:     ir2 = i; break;
            case 10:      ib2 = i; break;
            default: break;
        }
    }
    if (nbig == 2) {
        bool insertion = (big[0] == 0 && big[1] == 1 && iattr == 2);
        if (insertion) { ix = big[0]; iei = big[1]; }
        else           { iei = big[0]; ix = big[1]; }
    }

    const float* x     = (const float*)d_in[ix];
    const int*   ei    = (const int*)d_in[iei];      // int32 edge_index
    const float* attr  = (const float*)d_in[iattr];
    const float* W1    = (const float*)d_in[iW1];
    const float* root1 = (const float*)d_in[ir1];
    const float* b1    = (const float*)d_in[ib1];
    const float* W2    = (const float*)d_in[iW2];
    const float* root2 = (const float*)d_in[ir2];
    const float* b2    = (const float*)d_in[ib2];
    float* out = (float*)d_out;

    node1_kernel<<<(NN + 255) / 256, 256>>>(x, W1, root1, b1, ei);
    edge1_kernel<<<(EE * 4) / 256, 256>>>(ei, attr);       // exact grid: 25000
    node2_kernel<<<(NN + 255) / 256, 256>>>(W2, root2, b2);
    edge2_kernel<<<(EE * 4) / 256, 256>>>(ei, attr);
    out_kernel<<<(NN + 255) / 256, 256>>>(out);
}